// round 8
// baseline (speedup 1.0000x reference)
#include <cuda_runtime.h>
#include <cuda_bf16.h>
#include <cstdint>

// FirstSpikeDetector: out[b][t] = 1 iff spike_train[b][t] is the first nonzero
// in row b, else 0. Input values are exact 0.0f / 1.0f.
//
// R8: overlap the bulk zero-fill with the detector.
//  - 2D memset node zeros bytes [512, 8192) of each row (width 7680B,
//    pitch 8192B, height 16384) -- the driver fill path measured ~6.3 TB/s
//    in R7, faster than any SM store stream from R1-R6.
//  - Detector kernel (forked branch, concurrent with the memset) owns output
//    bytes [0, 512) per row: reads the first 128 elements, ballots, and
//    writes that 512B region as a one-hot float4 stream. Byte-disjoint from
//    the memset -> safe to run in parallel.
//  - Rare rows (first spike beyond element 127, P ~ 1.4e-6/row) can't write
//    into the memset region concurrently; the detector records the index in
//    a __device__ scratch array (written for EVERY row every call ->
//    deterministic across graph replays). A tiny fixup kernel, ordered after
//    BOTH branches, writes those 1.0f's.
// Critical path: max(memset ~20us, detector ~7us) + fixup ~2us.

static constexpr int T    = 2048;    // time steps per row
static constexpr int TV4  = T / 4;   // float4s per row (512)
static constexpr int ROWS = 16384;
static constexpr int WIN  = 128;     // detector-owned prefix (elements)

__device__ int g_fixup_idx[ROWS];    // -1 = handled by detector; else spike idx

__global__ void __launch_bounds__(256)
first_spike_detect(const float* __restrict__ in, float* __restrict__ out, int rows)
{
    const int gtid = blockIdx.x * blockDim.x + threadIdx.x;
    const int warp = gtid >> 5;
    const int lane = gtid & 31;
    if (warp >= rows) return;

    const float4* __restrict__ row_in =
        reinterpret_cast<const float4*>(in) + (size_t)warp * TV4;
    float4* __restrict__ row_out =
        reinterpret_cast<float4*>(out) + (size_t)warp * TV4;

    // ---- scan elements 0..127 (1 x LDG.128 per lane) ----
    float4 v = row_in[lane];
    const bool any = (v.x != 0.0f) | (v.y != 0.0f) | (v.z != 0.0f) | (v.w != 0.0f);
    const unsigned m = __ballot_sync(0xffffffffu, any);

    int f = -1;                       // warp-uniform first-spike index in window
    if (m != 0u) {
        const int src = __ffs(m) - 1;
        int sub = 0;
        if      (v.x != 0.0f) sub = 0;
        else if (v.y != 0.0f) sub = 1;
        else if (v.z != 0.0f) sub = 2;
        else                  sub = 3;
        sub = __shfl_sync(0xffffffffu, sub, src);
        f = (src << 2) + sub;
    }

    // ---- write the detector-owned 512B prefix as one-hot float4s ----
    {
        const int base = lane << 2;   // float index of this lane's vector
        float4 w;
        w.x = (base + 0 == f) ? 1.0f : 0.0f;
        w.y = (base + 1 == f) ? 1.0f : 0.0f;
        w.z = (base + 2 == f) ? 1.0f : 0.0f;
        w.w = (base + 3 == f) ? 1.0f : 0.0f;
        row_out[lane] = w;
    }

    if (m != 0u) {
        if (lane == 0) g_fixup_idx[warp] = -1;
        return;
    }

    // Rare path: first spike beyond the window (or none). Find it, park it.
    int first = -1;
    #pragma unroll 1
    for (int base = WIN; base < T; base += 128) {
        float4 u = row_in[(base >> 2) + lane];
        bool a2 = (u.x != 0.0f) | (u.y != 0.0f) | (u.z != 0.0f) | (u.w != 0.0f);
        unsigned m2 = __ballot_sync(0xffffffffu, a2);
        if (m2) {
            int s2 = __ffs(m2) - 1;
            int sub = 0;
            if (lane == s2) {
                if      (u.x != 0.0f) sub = 0;
                else if (u.y != 0.0f) sub = 1;
                else if (u.z != 0.0f) sub = 2;
                else                  sub = 3;
            }
            sub = __shfl_sync(0xffffffffu, sub, s2);
            first = base + (s2 << 2) + sub;
            break;
        }
    }
    if (lane == 0) g_fixup_idx[warp] = first;   // -1 if the row never spikes
}

__global__ void __launch_bounds__(256)
first_spike_fixup(float* __restrict__ out, int rows)
{
    const int row = blockIdx.x * blockDim.x + threadIdx.x;
    if (row >= rows) return;
    const int idx = g_fixup_idx[row];
    if (idx >= 0) {
        out[(size_t)row * T + idx] = 1.0f;
    }
}

extern "C" void kernel_launch(void* const* d_in, const int* in_sizes, int n_in,
                              void* d_out, int out_size)
{
    const float* in = (const float*)d_in[0];
    float* out = (float*)d_out;
    const int rows = in_sizes[0] / T;   // 16384

    // One-time host-side resources (streams/events are not device memory).
    static cudaStream_t s_side = nullptr;
    static cudaEvent_t  ev_fork = nullptr, ev_join = nullptr;
    if (s_side == nullptr) {
        cudaStreamCreateWithFlags(&s_side, cudaStreamNonBlocking);
        cudaEventCreateWithFlags(&ev_fork, cudaEventDisableTiming);
        cudaEventCreateWithFlags(&ev_join, cudaEventDisableTiming);
    }

    // ---- fork: side stream joins the capture ----
    cudaEventRecord(ev_fork, 0);
    cudaStreamWaitEvent(s_side, ev_fork, 0);

    // Branch A (main stream): 2D memset over bytes [512, 8192) of each row.
    cudaMemset2DAsync(reinterpret_cast<char*>(out) + WIN * sizeof(float),
                      (size_t)T * sizeof(float),          // pitch  = 8192 B
                      0,
                      (size_t)(T - WIN) * sizeof(float),  // width  = 7680 B
                      (size_t)rows,                       // height = 16384
                      0);

    // Branch B (side stream): detector owns bytes [0, 512) of each row.
    {
        const int threads = 256;
        const int blocks  = (rows * 32 + threads - 1) / threads;  // 2048
        first_spike_detect<<<blocks, threads, 0, s_side>>>(in, out, rows);
    }

    // ---- join: main stream waits on the detector ----
    cudaEventRecord(ev_join, s_side);
    cudaStreamWaitEvent(0, ev_join, 0);

    // Fixup (depends on memset via program order and detector via event).
    {
        const int threads = 256;
        const int blocks  = (rows + threads - 1) / threads;       // 64
        first_spike_fixup<<<blocks, threads>>>(out, rows);
    }
}

// round 9
// speedup vs baseline: 1.1061x; 1.1061x over previous
#include <cuda_runtime.h>
#include <cuda_bf16.h>
#include <cstdint>

// FirstSpikeDetector: out[b][t] = 1 iff spike_train[b][t] is the first nonzero
// in row b, else 0. Input values are exact 0.0f / 1.0f.
//
// R9 = R7's winning 2-node serial shape (1D full memset at ~6.3 TB/s, then a
// sparse detector that writes ONE 1.0f per row), with the detector rebuilt
// for latency instead of parallelism:
//   - 8 rows per warp: 8 independent LDG.128s issued back-to-back (MLP=8)
//     before any resolution -> one exposed DRAM latency instead of eight.
//   - 2048 warps total (256 blocks x 256 thr) -> 0.43 waves, no wave tail
//     (R7's detector ran 16384 warps = 1.73 waves and took 6.7us).
//   - Resolution: ballot + elected scalar store per row (zeros already laid
//     by the memset). Rare rows (P ~ 1.4e-6) continue scanning in chunks.
// R8 lesson folded in: no 2D memset, no fork/join, no third node (each small
// node costs ~4-5us of fixed overhead).

static constexpr int T    = 2048;    // time steps per row
static constexpr int TV4  = T / 4;   // float4s per row (512)
static constexpr int RPW  = 8;       // rows per warp

__device__ __forceinline__ void rare_scan_and_store(
    const float4* __restrict__ row_in, float* __restrict__ row_out, int lane)
{
    // First spike not in elements 0..127 (P ~ 1.4e-6 per row).
    #pragma unroll 1
    for (int base = 128; base < T; base += 128) {
        float4 u = row_in[(base >> 2) + lane];
        bool a2 = (u.x != 0.0f) | (u.y != 0.0f) | (u.z != 0.0f) | (u.w != 0.0f);
        unsigned m2 = __ballot_sync(0xffffffffu, a2);
        if (m2) {
            int s2 = __ffs(m2) - 1;
            if (lane == s2) {
                int sub;
                if      (u.x != 0.0f) sub = 0;
                else if (u.y != 0.0f) sub = 1;
                else if (u.z != 0.0f) sub = 2;
                else                  sub = 3;
                row_out[base + (s2 << 2) + sub] = 1.0f;
            }
            return;   // m2 is warp-uniform; all lanes exit together
        }
    }
    // No spike in the row: memset zeros are the correct output.
}

__global__ void __launch_bounds__(256)
first_spike_detect(const float* __restrict__ in, float* __restrict__ out, int rows)
{
    const int gtid = blockIdx.x * blockDim.x + threadIdx.x;
    const int warp = gtid >> 5;
    const int lane = gtid & 31;

    const int r0 = warp * RPW;
    if (r0 >= rows) return;

    const float4* __restrict__ in4 = reinterpret_cast<const float4*>(in);

    // ---- issue 8 independent chunk-0 loads back-to-back (MLP = 8) ----
    float4 v[RPW];
    #pragma unroll
    for (int k = 0; k < RPW; k++) {
        v[k] = in4[(size_t)(r0 + k) * TV4 + lane];
    }

    // ---- resolve each row: ballot + elected scalar store ----
    #pragma unroll
    for (int k = 0; k < RPW; k++) {
        const int row = r0 + k;
        float* __restrict__ row_out = out + (size_t)row * T;

        const bool any = (v[k].x != 0.0f) | (v[k].y != 0.0f) |
                         (v[k].z != 0.0f) | (v[k].w != 0.0f);
        const unsigned m = __ballot_sync(0xffffffffu, any);

        if (m != 0u) {
            const int src = __ffs(m) - 1;
            if (lane == src) {
                int sub;
                if      (v[k].x != 0.0f) sub = 0;
                else if (v[k].y != 0.0f) sub = 1;
                else if (v[k].z != 0.0f) sub = 2;
                else                     sub = 3;
                row_out[(src << 2) + sub] = 1.0f;
            }
        } else {
            rare_scan_and_store(in4 + (size_t)row * TV4, row_out, lane);
        }
    }
}

extern "C" void kernel_launch(void* const* d_in, const int* in_sizes, int n_in,
                              void* d_out, int out_size)
{
    const float* in = (const float*)d_in[0];
    float* out = (float*)d_out;
    const int rows = in_sizes[0] / T;   // 16384

    // Node 1: contiguous 1D zero fill (driver fill path, ~6.3 TB/s in R7).
    cudaMemsetAsync(d_out, 0, (size_t)out_size * sizeof(float), 0);

    // Node 2: latency-optimized sparse detector (8 rows/warp, MLP=8).
    const int warps   = (rows + RPW - 1) / RPW;            // 2048
    const int threads = 256;                               // 8 warps/block
    const int blocks  = (warps * 32 + threads - 1) / threads;  // 256
    first_spike_detect<<<blocks, threads>>>(in, out, rows);
}